// round 15
// baseline (speedup 1.0000x reference)
#include <cuda_runtime.h>
#include <cuda_bf16.h>

// ---------------------------------------------------------------------------
// Net_4174708212167: 4-qubit circuit per 2x2 patch + MLP, fully fused.
// Circuit = Rx-encoding (real tensor-product vector rv[16] x column phases
// (-i)^popcount) followed by a FIXED 16x16 unitary W (weights only).
// Per block (one image, 256 threads):
//  (1) stage image + build 20 composed SU(2) gates
//  (A) warp 0: evolve 16 basis columns through gate chain (2-lane split rep)
//      -> W' (phase-folded) in shared   || CONCURRENTLY threads 32..227:
//      sincospif encoding -> rv[16] in registers
//  (2) threads 32..227: f = W' rv (complex 16x16 matvec from shared),
//      <Z_q> from |f|^2 -> features
//  (3) FC1 64x784 split-K 4 + ReLU, (4) FC2 10x64
// ---------------------------------------------------------------------------

#define NPATCH 196
#define FEAT_DIM 784
#define FULLMASK 0xFFFFFFFFu

// --- local 1-qubit gate on 8-amplitude half-statevector (split rep) --------
__device__ __forceinline__ void gate_u8(float* re, float* im, int m, const float* u) {
    const float4* u4 = reinterpret_cast<const float4*>(u);
    float4 ua = u4[0];           // u00r u00i u01r u01i
    float4 ub = u4[1];           // u10r u10i u11r u11i
#pragma unroll
    for (int l = 0; l < 8; ++l) {
        if (l & m) continue;
        int k = l | m;
        float jr = re[l], ji = im[l], kr = re[k], ki = im[k];
        re[l] = ua.x * jr - ua.y * ji + ua.z * kr - ua.w * ki;
        im[l] = ua.x * ji + ua.y * jr + ua.z * ki + ua.w * kr;
        re[k] = ub.x * jr - ub.y * ji + ub.z * kr - ub.w * ki;
        im[k] = ub.x * ji + ub.y * jr + ub.z * ki + ub.w * kr;
    }
}

// General U on the split qubit: mine_new = U[b][b]*mine + U[b][1-b]*partner
__device__ __forceinline__ void cross_u(float* re, float* im, const float* u, int b) {
    const float4* u4 = reinterpret_cast<const float4*>(u);
    float4 row = u4[b];                         // row b of U
    float dr = b ? row.z : row.x, di = b ? row.w : row.y;   // diag element
    float orr = b ? row.x : row.z, oi = b ? row.y : row.w;  // off-diag
    float pr[8], pim[8];
#pragma unroll
    for (int l = 0; l < 8; ++l) {
        pr[l]  = __shfl_xor_sync(FULLMASK, re[l], 1);
        pim[l] = __shfl_xor_sync(FULLMASK, im[l], 1);
    }
#pragma unroll
    for (int l = 0; l < 8; ++l) {
        float r = re[l], i = im[l];
        re[l] = dr * r - di * i + orr * pr[l] - oi * pim[l];
        im[l] = dr * i + di * r + orr * pim[l] + oi * pr[l];
    }
}

__device__ __forceinline__ void swapf(float& a, float& b) { float t = a; a = b; b = t; }

// ---------------------------------------------------------------------------
__global__ void __launch_bounds__(256, 1)
fused_kernel(const float* __restrict__ x, const float* __restrict__ wts,
             const float* __restrict__ w1, const float* __restrict__ b1,
             const float* __restrict__ w2, const float* __restrict__ b2,
             float* __restrict__ out) {
    __shared__ __align__(16) float sx[FEAT_DIM];   // image pixels
    __shared__ __align__(16) float su[20][8];      // composed U per (layer,qubit)
    __shared__ __align__(16) float swr[16][16];    // Re W' (phase-folded) [col][row]
    __shared__ __align__(16) float swi[16][16];    // Im W'
    __shared__ __align__(16) float sf[FEAT_DIM];   // circuit features
    __shared__ float spart[256];                   // FC1 partial sums
    __shared__ float sh[64];                       // FC1 activations

    const int bid = blockIdx.x;
    const int t = threadIdx.x;

    // ---- phase 1: stage image + build composed gate matrices ----
    {
        const float4* img4 = reinterpret_cast<const float4*>(x + bid * FEAT_DIM);
        float4* sx4 = reinterpret_cast<float4*>(sx);
        if (t < FEAT_DIM / 4) sx4[t] = img4[t];
    }
    if (t < 20) {
        int l = t >> 2, qq = t & 3;
        float a  = wts[l * 12 + qq];
        float bb = wts[l * 12 + 4 + qq];
        float c  = wts[l * 12 + 8 + qq];
        float sa, ca, sb, cb, sc, cc;
        sincosf(0.5f * a,  &sa, &ca);
        sincosf(0.5f * bb, &sb, &cb);
        sincosf(0.5f * c,  &sc, &cc);
        // M = Rz(b)*Ry(a)
        float m00r =  cb * ca, m00i = -sb * ca;
        float m01r = -cb * sa, m01i =  sb * sa;
        float m10r =  cb * sa, m10i =  sb * sa;
        float m11r =  cb * ca, m11i =  sb * ca;
        // U = Ry(c)*M
        su[t][0] = cc * m00r - sc * m10r;  su[t][1] = cc * m00i - sc * m10i;
        su[t][2] = cc * m01r - sc * m11r;  su[t][3] = cc * m01i - sc * m11i;
        su[t][4] = sc * m00r + cc * m10r;  su[t][5] = sc * m00i + cc * m10i;
        su[t][6] = sc * m01r + cc * m11r;  su[t][7] = sc * m01i + cc * m11i;
    }
    __syncthreads();

    // ---- phase A || encoding: warp 0 builds W'; threads 32..227 build rv ----
    const int p = t - 32;                 // patch id for encoding threads
    float rv[16];

    if (t < 32) {
        // ---- W' build: 2 lanes per basis column c, split bit b = q3 ----
        const int c = t >> 1;
        const int b = t & 1;
        float re[8], im[8];
#pragma unroll
        for (int i = 0; i < 8; ++i) { re[i] = 0.f; im[i] = 0.f; }
        if ((c & 1) == b) re[c >> 1] = 1.f;

#pragma unroll
        for (int layer = 0; layer < 5; ++layer) {
            gate_u8(re, im, 4, su[layer * 4 + 0]);          // q0
            gate_u8(re, im, 2, su[layer * 4 + 1]);          // q1
            gate_u8(re, im, 1, su[layer * 4 + 2]);          // q2
            cross_u(re, im, su[layer * 4 + 3], b);          // q3
            if (layer < 4) {
                // CNOT(0,1): local bit4 controls swap of bit2
                swapf(re[4], re[6]); swapf(im[4], im[6]);
                swapf(re[5], re[7]); swapf(im[5], im[7]);
                // CNOT(1,2): local bit2 controls swap of bit1
                swapf(re[2], re[3]); swapf(im[2], im[3]);
                swapf(re[6], re[7]); swapf(im[6], im[7]);
                // CNOT(2,3): local bit1=1 amps exchange with partner lane
#pragma unroll
                for (int l = 1; l < 8; l += 2) {
                    re[l] = __shfl_xor_sync(FULLMASK, re[l], 1);
                    im[l] = __shfl_xor_sync(FULLMASK, im[l], 1);
                }
                // CNOT(3,0): split bit (b) controls swap of local bit4
#pragma unroll
                for (int l = 0; l < 4; ++l) {
                    float r0 = re[l], r1 = re[l + 4];
                    re[l] = b ? r1 : r0;  re[l + 4] = b ? r0 : r1;
                    float i0 = im[l], i1 = im[l + 4];
                    im[l] = b ? i1 : i0;  im[l + 4] = b ? i0 : i1;
                }
            }
        }

        // fold column phase (-i)^popcount(c) and store
        int k = __popc(c) & 3;
#pragma unroll
        for (int l = 0; l < 8; ++l) {
            int r = (l << 1) | b;
            float fr = re[l], fi = im[l], gr, gi;
            if      (k == 0) { gr =  fr; gi =  fi; }
            else if (k == 1) { gr =  fi; gi = -fr; }
            else if (k == 2) { gr = -fr; gi = -fi; }
            else             { gr = -fi; gi =  fr; }
            swr[c][r] = gr;
            swi[c][r] = gi;
        }
    } else if (p < NPATCH) {
        // ---- encoding: rv[idx] = prod_q (bit_q ? sin : cos)(pi x_q) ----
        int pi = p / 14;
        int pj = p - pi * 14;
        float a0 = sx[(2 * pi) * 28 + 2 * pj];
        float a1 = sx[(2 * pi) * 28 + 2 * pj + 1];
        float a2 = sx[(2 * pi + 1) * 28 + 2 * pj];
        float a3 = sx[(2 * pi + 1) * 28 + 2 * pj + 1];

        float c0, s0, c1, s1, c2, s2, c3, s3;
        sincospif(a0, &s0, &c0);
        sincospif(a1, &s1, &c1);
        sincospif(a2, &s2, &c2);
        sincospif(a3, &s3, &c3);

        float p01[4] = { c0 * c1, c0 * s1, s0 * c1, s0 * s1 };
        float p23[4] = { c2 * c3, c2 * s3, s2 * c3, s2 * s3 };
#pragma unroll
        for (int i = 0; i < 4; ++i)
#pragma unroll
            for (int jj = 0; jj < 4; ++jj)
                rv[i * 4 + jj] = p01[i] * p23[jj];   // idx bits: q0=8,q1=4,q2=2,q3=1
    }
    __syncthreads();

    // ---- phase 2: f = W' rv, <Z_q> from |f|^2 ----
    if (t >= 32 && p < NPATCH) {
        float fr[16], fi[16];
#pragma unroll
        for (int r = 0; r < 16; ++r) { fr[r] = 0.f; fi[r] = 0.f; }
#pragma unroll
        for (int c = 0; c < 16; ++c) {
            float av = rv[c];
            const float4* wr4 = reinterpret_cast<const float4*>(swr[c]);
            const float4* wi4 = reinterpret_cast<const float4*>(swi[c]);
#pragma unroll
            for (int rr = 0; rr < 4; ++rr) {
                float4 wr = wr4[rr];
                float4 wi = wi4[rr];
                fr[rr * 4 + 0] += av * wr.x;  fi[rr * 4 + 0] += av * wi.x;
                fr[rr * 4 + 1] += av * wr.y;  fi[rr * 4 + 1] += av * wi.y;
                fr[rr * 4 + 2] += av * wr.z;  fi[rr * 4 + 2] += av * wi.z;
                fr[rr * 4 + 3] += av * wr.w;  fi[rr * 4 + 3] += av * wi.w;
            }
        }

        float e0 = 0.f, e1 = 0.f, e2 = 0.f, e3 = 0.f;
#pragma unroll
        for (int r = 0; r < 16; ++r) {
            float pr = fr[r] * fr[r] + fi[r] * fi[r];
            e0 += (r & 8) ? -pr : pr;
            e1 += (r & 4) ? -pr : pr;
            e2 += (r & 2) ? -pr : pr;
            e3 += (r & 1) ? -pr : pr;
        }
        sf[p * 4 + 0] = e0;
        sf[p * 4 + 1] = e1;
        sf[p * 4 + 2] = e2;
        sf[p * 4 + 3] = e3;
    }
    __syncthreads();

    // ---- phase 3: FC1 (64 x 784), 4-way split-K, float4 ----
    {
        const int j = t & 63;          // output neuron
        const int q = t >> 6;          // K-quarter (196 floats = 49 float4)
        const float4* w4 = reinterpret_cast<const float4*>(w1 + j * FEAT_DIM + q * NPATCH);
        const float4* f4 = reinterpret_cast<const float4*>(sf + q * NPATCH);
        float acc = 0.f;
#pragma unroll
        for (int k = 0; k < NPATCH / 4; ++k) {
            float4 wv = w4[k];
            float4 fv = f4[k];
            acc += fv.x * wv.x + fv.y * wv.y + fv.z * wv.z + fv.w * wv.w;
        }
        spart[t] = acc;
    }
    __syncthreads();
    if (t < 64) {
        float acc = spart[t] + spart[64 + t] + spart[128 + t] + spart[192 + t] + b1[t];
        sh[t] = fmaxf(acc, 0.f);
    }
    __syncthreads();

    // ---- phase 4: FC2 (10 x 64) ----
    if (t < 10) {
        const float* w = w2 + t * 64;
        float acc = b2[t];
#pragma unroll
        for (int k = 0; k < 64; ++k) acc += sh[k] * w[k];
        out[bid * 10 + t] = acc;
    }
}

// ---------------------------------------------------------------------------
extern "C" void kernel_launch(void* const* d_in, const int* in_sizes, int n_in,
                              void* d_out, int out_size) {
    const float* x     = (const float*)d_in[0];
    const float* wts   = (const float*)d_in[1];
    const float* fc1_w = (const float*)d_in[2];
    const float* fc1_b = (const float*)d_in[3];
    const float* fc2_w = (const float*)d_in[4];
    const float* fc2_b = (const float*)d_in[5];
    float* out = (float*)d_out;

    int B = in_sizes[0] / FEAT_DIM;   // 128

    fused_kernel<<<B, 256>>>(x, wts, fc1_w, fc1_b, fc2_w, fc2_b, out);
}